// round 17
// baseline (speedup 1.0000x reference)
#include <cuda_runtime.h>
#include <cstdint>

// Problem constants
#define MDW   4
#define NB    2
#define NC    128
#define NH    64
#define NW    64
#define NF    16
#define NHW   4096
#define OUT1_ELEMS (NB*NF*4*NHW)        // 524288
#define WARP_ELEMS (NB*NC*NHW)          // 1048576

// cvol scratch: [b*F][uv=du*9+dv][h][w]  (42.5 MB)
__device__ float g_cvol[NB*NF*81*NHW];

typedef unsigned long long u64;

__device__ __forceinline__ u64 pk2(float x, float y) {
    u64 r; asm("mov.b64 %0, {%1,%2};" : "=l"(r) : "f"(x), "f"(y)); return r;
}
__device__ __forceinline__ float2 upk(u64 v) {
    float2 f; asm("mov.b64 {%0,%1}, %2;" : "=f"(f.x), "=f"(f.y) : "l"(v)); return f;
}
__device__ __forceinline__ u64 ffma2(u64 a, u64 b, u64 c) {
    u64 d; asm("fma.rn.f32x2 %0, %1, %2, %3;" : "=l"(d) : "l"(a), "l"(b), "l"(c)); return d;
}

// ---------------------------------------------------------------------------
// Kernel A: cost volume + channel projection (scalar FFMA2, high occupancy).
// grid (dv=9, hp=32, b=2), block 576 = 18 warps (wid = du*2 + xhalf),
// __launch_bounds__(576,2): 1152 thr/SM = 36 warps (9/SMSP), 56 regs.
// Thread tile: 2 pixels (rows h0,h0+1 at x = xhalf*32+lane) x 16 f.
// acc[8 fpair][2 row] u64 = 32 regs. Rows interleaved in smem -> LDS.64.
// Channels staged in 32-ch chunks:
//   ws[128][16] 8KB | refs[32][64][2] 16KB | tars[32][72][2] 18KB = 42KB/CTA
// ---------------------------------------------------------------------------
#define KC 32
#define NTHR 576
#define SMEM_A_BYTES ((2048 + 4096 + 4608) * 4)   // 43008

__global__ __launch_bounds__(NTHR, 2) void cvol_kernel(
    const float* __restrict__ ref, const float* __restrict__ tar,
    const float* __restrict__ pw)
{
    extern __shared__ float sm[];
    float* ws   = sm;               // [128][16]  ws[c][f] = pw[f][c]
    float* refs = sm + 2048;        // [KC][64][2]  (x-major, rows interleaved)
    float* tars = refs + 4096;      // [KC][72][2]  xw = x+4 window, borders 0

    const int dv = blockIdx.x, b = blockIdx.z;
    const int h0 = blockIdx.y * 2;
    const int tid  = threadIdx.x;
    const int wid  = tid >> 5;
    const int lane = tid & 31;
    const int du = wid >> 1;            // 0..8
    const int xh = wid & 1;
    const int x  = xh*32 + lane;        // 0..63

    // ws transposed: ws[c][f] = pw[f][c]
    for (int i = tid; i < 2048; i += NTHR)
        ws[i] = pw[(i & 15)*NC + (i >> 4)];
    // tar border words (xw 0..3, 68..71) x 2 rows x KC channels: zero once
    for (int i = tid; i < 512; i += NTHR) {
        int c = i >> 4, k = i & 15;
        int r = k & 1, kk = k >> 1;
        int xw = (kk < 4) ? kk : 64 + kk;
        tars[c*144 + xw*2 + r] = 0.f;
    }

    const int hr0 = h0 + dv - MDW;
    const bool ok0 = (hr0 >= 0) && (hr0 < NH);
    const bool ok1 = (hr0+1 >= 0) && (hr0+1 < NH);

    u64 acc[16];                    // [fp 0..7][row 0..1]
#pragma unroll
    for (int i = 0; i < 16; i++) acc[i] = 0ull;

    const float* refp = refs + 2*x;
    const float* tarp = tars + 2*(x + du);

    for (int ch = 0; ch < 4; ch++) {
        __syncthreads();   // previous chunk consumed / init done
        // stage refs: 32c x 16 xq, rows interleaved
        for (int i = tid; i < 512; i += NTHR) {
            int c = i >> 4, xq = i & 15;
            const float* g0 = &ref[((b*NC + ch*KC + c) << 12) + (h0 << 6) + 4*xq];
            float4 a = *(const float4*)g0;
            float4 bb = *(const float4*)(g0 + 64);
            float* d = &refs[c*128 + 8*xq];
            *(float2*)(d + 0) = make_float2(a.x, bb.x);
            *(float2*)(d + 2) = make_float2(a.y, bb.y);
            *(float2*)(d + 4) = make_float2(a.z, bb.z);
            *(float2*)(d + 6) = make_float2(a.w, bb.w);
        }
        // stage tars interior (xw 4..67), rows interleaved
        for (int i = tid; i < 512; i += NTHR) {
            int c = i >> 4, xq = i & 15;
            const float* gb = &tar[((b*NC + ch*KC + c) << 12) + 4*xq];
            float4 z = make_float4(0.f, 0.f, 0.f, 0.f);
            float4 a = ok0 ? *(const float4*)(gb + (hr0 << 6)) : z;
            float4 bb = ok1 ? *(const float4*)(gb + ((hr0+1) << 6)) : z;
            float* d = &tars[c*144 + 8 + 8*xq];
            *(float2*)(d + 0) = make_float2(a.x, bb.x);
            *(float2*)(d + 2) = make_float2(a.y, bb.y);
            *(float2*)(d + 4) = make_float2(a.z, bb.z);
            *(float2*)(d + 6) = make_float2(a.w, bb.w);
        }
        __syncthreads();

#pragma unroll 4
        for (int c = 0; c < KC; c++) {
            float2 rv = *(const float2*)&refp[c*128];   // (row0,row1) at x
            float2 tv = *(const float2*)&tarp[c*144];   // (row0,row1) at x+du-4
            float p0 = rv.x * tv.x;
            float p1 = rv.y * tv.y;
            float q0 = fmaxf(p0, 0.1f * p0);
            float q1 = fmaxf(p1, 0.1f * p1);
            u64 qa = pk2(q0, q0);
            u64 qb = pk2(q1, q1);
            const ulonglong2* wp = (const ulonglong2*)&ws[(ch*KC + c)*16];
#pragma unroll
            for (int k = 0; k < 4; k++) {
                ulonglong2 w = wp[k];
                acc[(2*k)*2 + 0]   = ffma2(qa, w.x, acc[(2*k)*2 + 0]);
                acc[(2*k)*2 + 1]   = ffma2(qb, w.x, acc[(2*k)*2 + 1]);
                acc[(2*k+1)*2 + 0] = ffma2(qa, w.y, acc[(2*k+1)*2 + 0]);
                acc[(2*k+1)*2 + 1] = ffma2(qb, w.y, acc[(2*k+1)*2 + 1]);
            }
        }
    }

    // epilogue: acc[fp][r] = (f=2fp, f=2fp+1) at pixel (h0+r, x)
    const int uv = du*9 + dv;
    const int p0 = (h0 << 6) + x;
    const int p1 = p0 + 64;
#pragma unroll
    for (int fp = 0; fp < 8; fp++) {
        float2 a0 = upk(acc[fp*2 + 0]);   // row0: (f0, f1)
        float2 a1 = upk(acc[fp*2 + 1]);   // row1: (f0, f1)
        int f0 = 2*fp;
        float* o0 = &g_cvol[(((b*NF + f0)*81 + uv) << 12)];
        float* o1 = o0 + (81 << 12);      // f0+1 plane
        o0[p0] = a0.x;  o0[p1] = a1.x;
        o1[p0] = a0.y;  o1[p1] = a1.y;
    }
}

// ---------------------------------------------------------------------------
// Kernel B: flow_reg (argmax -> 7x7 mask -> masked softmax -> soft-argmax + entropies)
// ---------------------------------------------------------------------------
__global__ __launch_bounds__(256) void flowreg_kernel(float* __restrict__ out)
{
    int g = blockIdx.x * 256 + threadIdx.x;     // 0..131071
    int bf = g >> 12, pix = g & 4095;
    const float* base = g_cvol + ((bf*81) << 12) + pix;

    float v[81];
#pragma unroll
    for (int i = 0; i < 81; i++) v[i] = base[i << 12];

    float m = v[0]; int am = 0;
#pragma unroll
    for (int i = 1; i < 81; i++) if (v[i] > m) { m = v[i]; am = i; }
    int ub = am / 9, vb = am - 9*(am/9);

    float S = 0.f, T = 0.f, Sx = 0.f, Sy = 0.f, gS = 0.f, gT = 0.f;
#pragma unroll
    for (int u = 0; u < 9; u++) {
#pragma unroll
        for (int w = 0; w < 9; w++) {
            float d = v[u*9 + w] - m;
            float e = __expf(d);
            gS += e; gT += e*d;
            bool inm = (abs(u - ub) <= 3) && (abs(w - vb) <= 3);
            if (inm) {
                S += e; T += e*d;
                Sx += e * (float)(u - 4);
                Sy += e * (float)(w - 4);
            }
        }
    }
    float inv  = 1.f / S;
    float ginv = 1.f / gS;
    float outx = Sx * inv;
    float outy = Sy * inv;
    float lent = (logf(S)  - T  * inv ) * 0.25694936f;   // 1/log(49)
    float gent = (logf(gS) - gT * ginv) * 0.22756237f;   // 1/log(81)

    out[(bf*4 + 0)*NHW + pix] = outx;
    out[(bf*4 + 1)*NHW + pix] = outy;
    out[(bf*4 + 2)*NHW + pix] = lent;
    out[(bf*4 + 3)*NHW + pix] = gent;
}

// ---------------------------------------------------------------------------
// Kernel C: bilinear backward warp of tar_feat by flow (hypothesis f=0)
// ---------------------------------------------------------------------------
__global__ __launch_bounds__(256) void warp_kernel(
    const float* __restrict__ tar, float* __restrict__ out)
{
    int g = blockIdx.x * 256 + threadIdx.x;       // 0..1048575
    int x = g & 63, y = (g >> 6) & 63, c = (g >> 12) & 127, b = g >> 19;

    const float* fbase = out + b*(NF*4*NHW) + (y << 6) + x;  // bf = b*16+0, ch 0/1
    float fx = fbase[0];
    float fy = fbase[NHW];

    float px = (float)x + fx;
    float py = (float)y + fy;
    bool inb = (fabsf(2.0f*px/63.0f - 1.0f) < 1.0f) &&
               (fabsf(2.0f*py/63.0f - 1.0f) < 1.0f);

    float x0f = floorf(px), y0f = floorf(py);
    float wx = px - x0f, wy = py - y0f;
    int x0 = (int)x0f, y0 = (int)y0f;

    const float* img = tar + ((b*NC + c) << 12);
    float s = 0.f;
#pragma unroll
    for (int dy = 0; dy < 2; dy++) {
#pragma unroll
        for (int dx = 0; dx < 2; dx++) {
            int xi = x0 + dx, yi = y0 + dy;
            bool ok = (xi >= 0) && (xi < NW) && (yi >= 0) && (yi < NH);
            float wgt = (dx ? wx : 1.f - wx) * (dy ? wy : 1.f - wy);
            int xc = min(max(xi, 0), NW-1), yc = min(max(yi, 0), NH-1);
            s += img[(yc << 6) + xc] * (ok ? wgt : 0.f);
        }
    }
    out[OUT1_ELEMS + g] = s * (inb ? 1.f : 0.f);
}

// ---------------------------------------------------------------------------
extern "C" void kernel_launch(void* const* d_in, const int* in_sizes, int n_in,
                              void* d_out, int out_size)
{
    const float* ref = (const float*)d_in[0];
    const float* tar = (const float*)d_in[1];
    const float* pw  = (const float*)d_in[2];
    float* out = (float*)d_out;

    cudaFuncSetAttribute(cvol_kernel,
                         cudaFuncAttributeMaxDynamicSharedMemorySize, SMEM_A_BYTES);

    dim3 gA(9, NH/2, NB);
    cvol_kernel<<<gA, NTHR, SMEM_A_BYTES>>>(ref, tar, pw);
    flowreg_kernel<<<(NB*NF*NHW)/256, 256>>>(out);
    warp_kernel<<<WARP_ELEMS/256, 256>>>(tar, out);
}